// round 8
// baseline (speedup 1.0000x reference)
#include <cuda_runtime.h>
#include <cstdint>

// LIF spike scan. x: [64, 8192, 100] fp32 (T contiguous) -> spikes (same shape).
//   mem = mem*TAU + x_t - w ; spike = (mem > THRESH)
//   w = BETA*w + (1-BETA)*(A*mem + B*spike) ; mem -= spike*THRESH
//
// R8: persistent grid, 8 CTAs/SM (1 warp each), double-buffered 12.8KB TMA
// tiles. Per iteration the next load is issued before compute (gated only on
// wait_group.read 0, i.e. prior stores' smem-read phase, which is long done),
// so each CTA always has a load in flight and exposes a store drain exactly
// once at kernel end instead of once per tile.

#define TAU    0.5f
#define THRESH 0.5f
#define BETA   0.9f
#define C_MS   0.05f   // (1-BETA)*A == (1-BETA)*B

constexpr int T_LEN       = 100;
constexpr int ROWS        = 32;                  // rows/tile == threads/CTA (1 warp)
constexpr int TILE_FLOATS = ROWS * T_LEN;        // 3200
constexpr int TILE_BYTES  = TILE_FLOATS * 4;     // 12800
constexpr int NBUF        = 2;
constexpr int DATA_OFF    = 32;                  // 2 mbarrier slots
constexpr int SMEM_BYTES  = DATA_OFF + NBUF * TILE_BYTES;   // 25,632 -> 8 CTAs/SM
constexpr int GRID        = 1216;                // 8 * 152 SMs

__device__ __forceinline__ void lif_step(float xt, float& mem, float& w, float& sp) {
    float m2 = fmaf(mem, TAU, xt) - w;
    bool fire = (m2 > THRESH);
    sp  = fire ? 1.0f : 0.0f;
    w   = fmaf(BETA, w, fmaf(C_MS, m2, C_MS * sp));
    mem = fire ? (m2 - THRESH) : m2;     // FSETP -> FSEL, short dep chain
}

__device__ __forceinline__ void mbar_wait_acq(uint32_t mbar, uint32_t phase) {
    uint32_t done;
    asm volatile(
        "{\n\t.reg .pred p;\n\t"
        "mbarrier.try_wait.parity.acquire.cta.shared::cta.b64 p, [%1], %2;\n\t"
        "selp.b32 %0, 1, 0, p;\n\t}"
        : "=r"(done) : "r"(mbar), "r"(phase) : "memory");
    if (!done) {
        asm volatile(
            "{\n\t.reg .pred P1;\n\t"
            "WL_%=:\n\t"
            "mbarrier.try_wait.parity.acquire.cta.shared::cta.b64 P1, [%0], %1, 0x989680;\n\t"
            "@P1 bra.uni WD_%=;\n\t"
            "bra.uni WL_%=;\n\t"
            "WD_%=:\n\t}"
            :: "r"(mbar), "r"(phase) : "memory");
    }
}

__device__ __forceinline__ void tma_load(uint32_t dsh, const float* g, uint32_t mbar) {
    asm volatile("mbarrier.arrive.expect_tx.shared.b64 _, [%0], %1;"
                 :: "r"(mbar), "r"((uint32_t)TILE_BYTES) : "memory");
    asm volatile("cp.async.bulk.shared::cta.global.mbarrier::complete_tx::bytes "
                 "[%0], [%1], %2, [%3];"
                 :: "r"(dsh), "l"(g), "r"((uint32_t)TILE_BYTES), "r"(mbar) : "memory");
}

__global__ __launch_bounds__(ROWS, 8) void lif_kernel(const float* __restrict__ x,
                                                      float* __restrict__ out,
                                                      int n_tiles) {
    extern __shared__ float smem[];
    const int tid = threadIdx.x;

    uint32_t sb;
    asm("{ .reg .u64 t; cvta.to.shared.u64 t, %1; cvt.u32.u64 %0, t; }"
        : "=r"(sb) : "l"(smem));

    if (tid == 0) {
        asm volatile("mbarrier.init.shared.b64 [%0], 1;" :: "r"(sb)      : "memory");
        asm volatile("mbarrier.init.shared.b64 [%0], 1;" :: "r"(sb + 16) : "memory");
        // Prologue: load this CTA's first tile into buffer 0.
        tma_load(sb + DATA_OFF, x + (size_t)blockIdx.x * TILE_FLOATS, sb);
    }
    __syncwarp();

    const int G = gridDim.x;
    uint32_t phases = 0;   // bit b = expected parity for buffer b
    int k = 0;
    for (int t = blockIdx.x; t < n_tiles; t += G, k++) {
        const int b = k & 1;
        const uint32_t mbar = sb + 16u * b;
        const uint32_t dsh  = sb + DATA_OFF + (uint32_t)b * TILE_BYTES;
        float* buf = smem + DATA_OFF / 4 + b * TILE_FLOATS;

        // Tile t's data ready.
        mbar_wait_acq(mbar, (phases >> b) & 1u);
        phases ^= (1u << b);

        // Issue the next load (buffer 1-b) before computing, so a load is in
        // flight during the whole compute+store phase. Gate only on prior
        // stores' smem reads (done long ago by the time this load's mbar
        // would fire anyway).
        const int tn = t + G;
        if (tid == 0 && tn < n_tiles) {
            asm volatile("cp.async.bulk.wait_group.read 0;" ::: "memory");
            const uint32_t bn = 1u - (uint32_t)b;
            tma_load(sb + DATA_OFF + bn * TILE_BYTES,
                     x + (size_t)tn * TILE_FLOATS, sb + 16u * bn);
        }

        // Scan: one thread per row; float4 smem access is bank-conflict-free
        // (100 % 32 == 4: each quarter-warp phase covers all 32 banks once).
        {
            float4* srow = reinterpret_cast<float4*>(buf + tid * T_LEN);
            float mem = 0.0f, w = 0.0f;
            #pragma unroll
            for (int j = 0; j < T_LEN / 4; j++) {
                float4 v = srow[j];
                float4 sp;
                lif_step(v.x, mem, w, sp.x);
                lif_step(v.y, mem, w, sp.y);
                lif_step(v.z, mem, w, sp.z);
                lif_step(v.w, mem, w, sp.w);
                srow[j] = sp;
            }
        }
        __syncwarp();

        // Async bulk store of tile t's spikes; no drain here.
        if (tid == 0) {
            asm volatile("fence.proxy.async.shared::cta;" ::: "memory");
            asm volatile("cp.async.bulk.global.shared::cta.bulk_group [%0], [%1], %2;"
                         :: "l"(out + (size_t)t * TILE_FLOATS), "r"(dsh),
                            "r"((uint32_t)TILE_BYTES) : "memory");
            asm volatile("cp.async.bulk.commit_group;" ::: "memory");
        }
        __syncwarp();
    }

    if (tid == 0)
        asm volatile("cp.async.bulk.wait_group 0;" ::: "memory");
}

extern "C" void kernel_launch(void* const* d_in, const int* in_sizes, int n_in,
                              void* d_out, int out_size) {
    const float* x = (const float*)d_in[0];
    float* out = (float*)d_out;
    int n_tiles = in_sizes[0] / TILE_FLOATS;   // 16384

    int grid = GRID < n_tiles ? GRID : n_tiles;
    cudaFuncSetAttribute(lif_kernel, cudaFuncAttributeMaxDynamicSharedMemorySize,
                         SMEM_BYTES);
    lif_kernel<<<grid, ROWS, SMEM_BYTES>>>(x, out, n_tiles);
}

// round 9
// speedup vs baseline: 1.1111x; 1.1111x over previous
#include <cuda_runtime.h>
#include <cstdint>

// LIF spike scan. x: [64, 8192, 100] fp32 (T contiguous) -> spikes (same shape).
//   mem = mem*TAU + x_t - w ; spike = (mem > THRESH)
//   w = BETA*w + (1-BETA)*(A*mem + B*spike) ; mem -= spike*THRESH
//
// R9 = R6 (best DRAM%: non-persistent, 64-row / 25.6KB tiles, 8 CTAs/SM,
// TMA bulk in/out, conflict-free float4 smem scan) with the exit drain relaxed
// to wait_group.read 0: the CTA frees its slot as soon as the TMA engine has
// finished READING smem; the GMEM writes drain under the kernel-end fence,
// overlapped with the replacement CTA's load.

#define TAU    0.5f
#define THRESH 0.5f
#define BETA   0.9f
#define C_MS   0.05f   // (1-BETA)*A == (1-BETA)*B

constexpr int T_LEN       = 100;
constexpr int ROWS        = 64;                  // rows/tile == threads/CTA
constexpr int TILE_FLOATS = ROWS * T_LEN;        // 6400
constexpr int TILE_BYTES  = TILE_FLOATS * 4;     // 25600
constexpr int DATA_OFF    = 16;                  // one mbarrier slot
constexpr int SMEM_BYTES  = DATA_OFF + TILE_BYTES;   // 25,616

__device__ __forceinline__ void lif_step(float xt, float& mem, float& w, float& sp) {
    float m2 = fmaf(mem, TAU, xt) - w;
    bool fire = (m2 > THRESH);
    sp  = fire ? 1.0f : 0.0f;
    w   = fmaf(BETA, w, fmaf(C_MS, m2, C_MS * sp));
    mem = fire ? (m2 - THRESH) : m2;     // FSETP -> FSEL, short dep chain
}

__global__ __launch_bounds__(ROWS, 8) void lif_kernel(const float* __restrict__ x,
                                                      float* __restrict__ out) {
    extern __shared__ float smem[];
    const int tid = threadIdx.x;

    uint32_t sb;
    asm("{ .reg .u64 t; cvta.to.shared.u64 t, %1; cvt.u32.u64 %0, t; }"
        : "=r"(sb) : "l"(smem));
    const uint32_t mbar = sb;
    const uint32_t dsh  = sb + DATA_OFF;
    float* buf = smem + DATA_OFF / 4;

    const float* __restrict__ xin  = x   + (size_t)blockIdx.x * TILE_FLOATS;
    float* __restrict__       xout = out + (size_t)blockIdx.x * TILE_FLOATS;

    if (tid == 0) {
        asm volatile("mbarrier.init.shared.b64 [%0], 1;" :: "r"(mbar) : "memory");
        asm volatile("mbarrier.arrive.expect_tx.shared.b64 _, [%0], %1;"
                     :: "r"(mbar), "r"((uint32_t)TILE_BYTES) : "memory");
        asm volatile("cp.async.bulk.shared::cta.global.mbarrier::complete_tx::bytes "
                     "[%0], [%1], %2, [%3];"
                     :: "r"(dsh), "l"(xin), "r"((uint32_t)TILE_BYTES),
                        "r"(mbar) : "memory");
    }
    __syncthreads();   // all threads see the initialized mbarrier

    // Wait for the load (parity 0), acquire for the LDS reads that follow.
    {
        uint32_t done;
        asm volatile(
            "{\n\t.reg .pred p;\n\t"
            "mbarrier.try_wait.parity.acquire.cta.shared::cta.b64 p, [%1], 0;\n\t"
            "selp.b32 %0, 1, 0, p;\n\t}"
            : "=r"(done) : "r"(mbar) : "memory");
        if (!done) {
            asm volatile(
                "{\n\t.reg .pred P1;\n\t"
                "WL_%=:\n\t"
                "mbarrier.try_wait.parity.acquire.cta.shared::cta.b64 P1, [%0], 0, 0x989680;\n\t"
                "@P1 bra.uni WD_%=;\n\t"
                "bra.uni WL_%=;\n\t"
                "WD_%=:\n\t}"
                :: "r"(mbar) : "memory");
        }
    }

    // Scan: one thread per row; float4 smem access is bank-conflict-free
    // (100 % 32 == 4: each quarter-warp phase covers all 32 banks once).
    {
        float4* srow = reinterpret_cast<float4*>(buf + tid * T_LEN);
        float mem = 0.0f, w = 0.0f;
        #pragma unroll
        for (int j = 0; j < T_LEN / 4; j++) {
            float4 v = srow[j];
            float4 sp;
            lif_step(v.x, mem, w, sp.x);
            lif_step(v.y, mem, w, sp.y);
            lif_step(v.z, mem, w, sp.z);
            lif_step(v.w, mem, w, sp.w);
            srow[j] = sp;
        }
    }
    __syncthreads();

    // Bulk store smem -> gmem. Wait only for the smem-READ phase before CTA
    // exit (safe: smem can be reused by the next CTA); the GMEM writes drain
    // under the kernel-end fence, overlapped with the next CTA's TMA load.
    if (tid == 0) {
        asm volatile("fence.proxy.async.shared::cta;" ::: "memory");
        asm volatile("cp.async.bulk.global.shared::cta.bulk_group [%0], [%1], %2;"
                     :: "l"(xout), "r"(dsh), "r"((uint32_t)TILE_BYTES) : "memory");
        asm volatile("cp.async.bulk.commit_group;" ::: "memory");
        asm volatile("cp.async.bulk.wait_group.read 0;" ::: "memory");
    }
}

extern "C" void kernel_launch(void* const* d_in, const int* in_sizes, int n_in,
                              void* d_out, int out_size) {
    const float* x = (const float*)d_in[0];
    float* out = (float*)d_out;
    int grid = in_sizes[0] / TILE_FLOATS;      // 8192

    cudaFuncSetAttribute(lif_kernel, cudaFuncAttributeMaxDynamicSharedMemorySize,
                         SMEM_BYTES);
    lif_kernel<<<grid, ROWS, SMEM_BYTES>>>(x, out);
}

// round 10
// speedup vs baseline: 1.1181x; 1.0063x over previous
#include <cuda_runtime.h>
#include <cstdint>

// LIF spike scan. x: [64, 8192, 100] fp32 (T contiguous) -> spikes (same shape).
//   mem = mem*TAU + x_t - w ; spike = (mem > THRESH)
//   w = BETA*w + (1-BETA)*(A*mem + B*spike) ; mem -= spike*THRESH
//
// R10 = R9 (non-persistent, 64-row / 25.6KB tiles, 8 CTAs/SM, TMA bulk in/out,
// conflict-free float4 smem scan, read-relaxed exit drain) + L2::cache_hint
// evict_first on both TMA directions: both streams are touch-once, so keep
// them out of L2's working set and let writebacks batch.

#define TAU    0.5f
#define THRESH 0.5f
#define BETA   0.9f
#define C_MS   0.05f   // (1-BETA)*A == (1-BETA)*B

constexpr int T_LEN       = 100;
constexpr int ROWS        = 64;                  // rows/tile == threads/CTA
constexpr int TILE_FLOATS = ROWS * T_LEN;        // 6400
constexpr int TILE_BYTES  = TILE_FLOATS * 4;     // 25600
constexpr int DATA_OFF    = 16;                  // one mbarrier slot
constexpr int SMEM_BYTES  = DATA_OFF + TILE_BYTES;   // 25,616

__device__ __forceinline__ void lif_step(float xt, float& mem, float& w, float& sp) {
    float m2 = fmaf(mem, TAU, xt) - w;
    bool fire = (m2 > THRESH);
    sp  = fire ? 1.0f : 0.0f;
    w   = fmaf(BETA, w, fmaf(C_MS, m2, C_MS * sp));
    mem = fire ? (m2 - THRESH) : m2;     // FSETP -> FSEL, short dep chain
}

__global__ __launch_bounds__(ROWS, 8) void lif_kernel(const float* __restrict__ x,
                                                      float* __restrict__ out) {
    extern __shared__ float smem[];
    const int tid = threadIdx.x;

    uint32_t sb;
    asm("{ .reg .u64 t; cvta.to.shared.u64 t, %1; cvt.u32.u64 %0, t; }"
        : "=r"(sb) : "l"(smem));
    const uint32_t mbar = sb;
    const uint32_t dsh  = sb + DATA_OFF;
    float* buf = smem + DATA_OFF / 4;

    const float* __restrict__ xin  = x   + (size_t)blockIdx.x * TILE_FLOATS;
    float* __restrict__       xout = out + (size_t)blockIdx.x * TILE_FLOATS;

    // Streaming L2 policy: evict_first for touch-once data.
    uint64_t pol;
    asm volatile("createpolicy.fractional.L2::evict_first.b64 %0, 1.0;" : "=l"(pol));

    if (tid == 0) {
        asm volatile("mbarrier.init.shared.b64 [%0], 1;" :: "r"(mbar) : "memory");
        asm volatile("mbarrier.arrive.expect_tx.shared.b64 _, [%0], %1;"
                     :: "r"(mbar), "r"((uint32_t)TILE_BYTES) : "memory");
        asm volatile("cp.async.bulk.shared::cta.global.mbarrier::complete_tx::bytes"
                     ".L2::cache_hint [%0], [%1], %2, [%3], %4;"
                     :: "r"(dsh), "l"(xin), "r"((uint32_t)TILE_BYTES),
                        "r"(mbar), "l"(pol) : "memory");
    }
    __syncthreads();   // all threads see the initialized mbarrier

    // Wait for the load (parity 0), acquire for the LDS reads that follow.
    {
        uint32_t done;
        asm volatile(
            "{\n\t.reg .pred p;\n\t"
            "mbarrier.try_wait.parity.acquire.cta.shared::cta.b64 p, [%1], 0;\n\t"
            "selp.b32 %0, 1, 0, p;\n\t}"
            : "=r"(done) : "r"(mbar) : "memory");
        if (!done) {
            asm volatile(
                "{\n\t.reg .pred P1;\n\t"
                "WL_%=:\n\t"
                "mbarrier.try_wait.parity.acquire.cta.shared::cta.b64 P1, [%0], 0, 0x989680;\n\t"
                "@P1 bra.uni WD_%=;\n\t"
                "bra.uni WL_%=;\n\t"
                "WD_%=:\n\t}"
                :: "r"(mbar) : "memory");
        }
    }

    // Scan: one thread per row; float4 smem access is bank-conflict-free
    // (100 % 32 == 4: each quarter-warp phase covers all 32 banks once).
    {
        float4* srow = reinterpret_cast<float4*>(buf + tid * T_LEN);
        float mem = 0.0f, w = 0.0f;
        #pragma unroll
        for (int j = 0; j < T_LEN / 4; j++) {
            float4 v = srow[j];
            float4 sp;
            lif_step(v.x, mem, w, sp.x);
            lif_step(v.y, mem, w, sp.y);
            lif_step(v.z, mem, w, sp.z);
            lif_step(v.w, mem, w, sp.w);
            srow[j] = sp;
        }
    }
    __syncthreads();

    // Bulk store smem -> gmem (streaming policy). Wait only for the
    // smem-READ phase before CTA exit; GMEM writes drain under the
    // kernel-end fence, overlapped with the replacement CTA's load.
    if (tid == 0) {
        asm volatile("fence.proxy.async.shared::cta;" ::: "memory");
        asm volatile("cp.async.bulk.global.shared::cta.bulk_group"
                     ".L2::cache_hint [%0], [%1], %2, %3;"
                     :: "l"(xout), "r"(dsh), "r"((uint32_t)TILE_BYTES),
                        "l"(pol) : "memory");
        asm volatile("cp.async.bulk.commit_group;" ::: "memory");
        asm volatile("cp.async.bulk.wait_group.read 0;" ::: "memory");
    }
}

extern "C" void kernel_launch(void* const* d_in, const int* in_sizes, int n_in,
                              void* d_out, int out_size) {
    const float* x = (const float*)d_in[0];
    float* out = (float*)d_out;
    int grid = in_sizes[0] / TILE_FLOATS;      // 8192

    cudaFuncSetAttribute(lif_kernel, cudaFuncAttributeMaxDynamicSharedMemorySize,
                         SMEM_BYTES);
    lif_kernel<<<grid, ROWS, SMEM_BYTES>>>(x, out);
}